// round 1
// baseline (speedup 1.0000x reference)
#include <cuda_runtime.h>

#define NN   100000
#define EE   1600000
#define CINF 16
#define HIDF 64
#define NG   192      // 3 live gates (i, c, o) x 64
#define KF   32       // feature dim: [x(16) | tx1(16)]

// ---------------- device scratch (no allocations allowed) ----------------
__device__ float  g_deg[NN];          // degree, then dinv in place
__device__ float4 g_tx1[NN * 4];      // [N][16] scatter accumulator (16B aligned rows)
__device__ float  g_Wc[KF * NG];      // combined gate weights
__device__ float  g_bias[NG];         // bx + bh + bg folded
__device__ float  g_wlin[HIDF];
__device__ float  g_wc2[HIDF];        // peephole for O gate
__device__ float  g_blin;
__device__ int    g_is64;             // edge_index dtype flag

// ---------------- dtype detection: int64 has zero high words ----------------
__global__ void k_detect(const int* ei32) {
    if (threadIdx.x == 0) {
        int is64 = 1;
        #pragma unroll
        for (int e = 0; e < 32; e++) {
            if (ei32[2 * e + 1] != 0) { is64 = 0; break; }
        }
        g_is64 = is64;
    }
}

// ---------------- fold params into combined weight/bias ----------------
// gates used: slot 0 -> g=0 (i), slot 1 -> g=2 (c), slot 2 -> g=3 (o)
__global__ void k_prep(const float* __restrict__ Wx, const float* __restrict__ bx,
                       const float* __restrict__ bh, const float* __restrict__ wc,
                       const float* __restrict__ bg, const float* __restrict__ Wlin,
                       const float* __restrict__ blin) {
    int t = threadIdx.x;
    for (int idx = t; idx < KF * NG; idx += blockDim.x) {
        int k = idx / NG, o = idx % NG;
        int s = o / HIDF, h = o % HIDF;
        int g = (s == 0) ? 0 : ((s == 1) ? 2 : 3);
        int kk = (k < CINF) ? 0 : 1;
        int kr = k & (CINF - 1);
        // Wx: [4][K=2][CIN][HID]
        g_Wc[idx] = Wx[((g * 2 + kk) * CINF + kr) * HIDF + h];
    }
    for (int idx = t; idx < NG; idx += blockDim.x) {
        int s = idx / HIDF, h = idx % HIDF;
        int g = (s == 0) ? 0 : ((s == 1) ? 2 : 3);
        g_bias[idx] = bx[g * HIDF + h] + bh[g * HIDF + h] + bg[g * HIDF + h];
    }
    if (t < HIDF) {
        g_wlin[t] = Wlin[t];         // [HID,1]
        g_wc2[t]  = wc[2 * HIDF + t];
    }
    if (t == 0) g_blin = blin[0];
}

// ---------------- zero accumulators ----------------
__global__ void k_zero() {
    int i = blockIdx.x * blockDim.x + threadIdx.x;
    if (i < NN) g_deg[i] = 0.f;
    if (i < NN * 4) g_tx1[i] = make_float4(0.f, 0.f, 0.f, 0.f);
}

// ---------------- degree ----------------
__global__ void k_deg(const void* __restrict__ ei, const float* __restrict__ w) {
    int e = blockIdx.x * blockDim.x + threadIdx.x;
    if (e >= EE) return;
    int r = g_is64 ? (int)((const long long*)ei)[e] : ((const int*)ei)[e];
    atomicAdd(&g_deg[r], w[e]);
}

__global__ void k_dinv() {
    int i = blockIdx.x * blockDim.x + threadIdx.x;
    if (i < NN) {
        float d = g_deg[i];
        g_deg[i] = (d > 0.f) ? rsqrtf(d) : 0.f;
    }
}

// ---------------- scatter: tx1[row] += norm * x[col] ----------------
__global__ void k_scatter(const void* __restrict__ ei, const float* __restrict__ w,
                          const float* __restrict__ x) {
    int e = blockIdx.x * blockDim.x + threadIdx.x;
    if (e >= EE) return;
    int r, c;
    if (g_is64) {
        r = (int)((const long long*)ei)[e];
        c = (int)((const long long*)ei)[EE + e];
    } else {
        r = ((const int*)ei)[e];
        c = ((const int*)ei)[EE + e];
    }
    float nm = -(g_deg[r] * w[e] * g_deg[c]);
    if (nm == 0.f) return;
    const float4* x4 = (const float4*)x;
    float4* dst = &g_tx1[r * 4];
    #pragma unroll
    for (int q = 0; q < 4; q++) {
        float4 v = x4[c * 4 + q];
        asm volatile("red.global.add.v4.f32 [%0], {%1, %2, %3, %4};"
                     :: "l"(dst + q),
                        "f"(v.x * nm), "f"(v.y * nm), "f"(v.z * nm), "f"(v.w * nm)
                     : "memory");
    }
}

// ---------------- dense gates + LSTM nonlinearity + output projection ----------------
// 192 threads/block, each thread owns one output column (W column in registers).
// 3 nodes per iteration; features broadcast from SMEM.
__global__ void __launch_bounds__(192) k_gate(const float* __restrict__ x,
                                              float* __restrict__ out) {
    __shared__ float fsm[3][KF];
    __shared__ float gsm[3 * NG];
    __shared__ float wl[HIDF], w2[HIDF];
    __shared__ float rsm[3][2];

    int t = threadIdx.x;
    float w[KF];
    #pragma unroll
    for (int k = 0; k < KF; k++) w[k] = g_Wc[k * NG + t];
    float bias = g_bias[t];
    if (t < HIDF) { wl[t] = g_wlin[t]; w2[t] = g_wc2[t]; }
    float blin = g_blin;
    const float* tx = (const float*)g_tx1;

    for (int base = blockIdx.x * 3; base < NN; base += gridDim.x * 3) {
        // load features for up to 3 nodes
        if (t < 96) {
            int j = t >> 5, k = t & 31;
            int node = base + j;
            float v = 0.f;
            if (node < NN)
                v = (k < CINF) ? x[node * CINF + k] : tx[node * CINF + (k - CINF)];
            fsm[j][k] = v;
        }
        __syncthreads();

        float a0 = bias, a1 = bias, a2 = bias;
        #pragma unroll
        for (int k = 0; k < KF; k++) {
            float wk = w[k];
            a0 += fsm[0][k] * wk;
            a1 += fsm[1][k] * wk;
            a2 += fsm[2][k] * wk;
        }
        gsm[0 * NG + t] = a0;
        gsm[1 * NG + t] = a1;
        gsm[2 * NG + t] = a2;
        __syncthreads();

        // combine: thread group j = t/64 handles node base+j, channel ch = t%64
        int j = t >> 6, ch = t & 63;
        float gi = gsm[j * NG + ch];
        float gc = gsm[j * NG + 64 + ch];
        float go = gsm[j * NG + 128 + ch];
        float I = 1.f / (1.f + __expf(-gi));
        float C = I * tanhf(gc);
        float O = 1.f / (1.f + __expf(-(go + w2[ch] * C)));
        float H = O * tanhf(C);
        float p = H * wl[ch];
        #pragma unroll
        for (int off = 16; off > 0; off >>= 1)
            p += __shfl_xor_sync(0xffffffffu, p, off);
        if ((t & 31) == 0) rsm[j][(t >> 5) & 1] = p;
        __syncthreads();

        if (t < 3) {
            int node = base + t;
            if (node < NN) out[node] = rsm[t][0] + rsm[t][1] + blin;
        }
    }
}

// ---------------- launch ----------------
extern "C" void kernel_launch(void* const* d_in, const int* in_sizes, int n_in,
                              void* d_out, int out_size) {
    const float* x    = (const float*)d_in[0];
    const void*  ei   = d_in[1];
    const float* w    = (const float*)d_in[2];
    const float* Wx   = (const float*)d_in[3];
    const float* bx   = (const float*)d_in[4];
    // d_in[5] = Wh: provably unused (H0 = 0)
    const float* bh   = (const float*)d_in[6];
    const float* wc   = (const float*)d_in[7];
    const float* bg   = (const float*)d_in[8];
    const float* Wlin = (const float*)d_in[9];
    const float* blin = (const float*)d_in[10];
    float* out = (float*)d_out;

    k_detect<<<1, 32>>>((const int*)ei);
    k_prep<<<1, 256>>>(Wx, bx, bh, wc, bg, Wlin, blin);
    k_zero<<<(NN * 4 + 255) / 256, 256>>>();
    k_deg<<<(EE + 255) / 256, 256>>>(ei, w);
    k_dinv<<<(NN + 255) / 256, 256>>>();
    k_scatter<<<(EE + 255) / 256, 256>>>(ei, w, x);
    k_gate<<<1184, 192>>>(x, out);
}

// round 2
// speedup vs baseline: 1.1059x; 1.1059x over previous
#include <cuda_runtime.h>

#define NN   100000
#define EE   1600000
#define CINF 16
#define HIDF 64
#define NG   192      // 3 live gates (i, c, o) x 64
#define KF   32       // feature dim: [x(16) | tx1(16)]

// ---------------- device scratch (no allocations allowed) ----------------
__device__ float  g_deg[NN];          // degree, then dinv in place
__device__ float4 g_tx1[NN * 4];      // [N][16] scatter accumulator (no dinv[row] factor)
__device__ float  g_Wc[KF * NG];      // combined gate weights
__device__ float  g_bias[NG];         // bx + bh + bg folded
__device__ float  g_wlin[HIDF];
__device__ float  g_wc2[HIDF];        // peephole for O gate
__device__ float  g_blin;
__device__ int    g_is64;             // edge_index dtype flag

// ---------------- dtype detection: int64 has zero high words ----------------
__global__ void k_detect(const int* ei32) {
    if (threadIdx.x == 0) {
        int is64 = 1;
        #pragma unroll
        for (int e = 0; e < 32; e++) {
            if (ei32[2 * e + 1] != 0) { is64 = 0; break; }
        }
        g_is64 = is64;
    }
}

// ---------------- fold params into combined weight/bias ----------------
// gates used: slot 0 -> g=0 (i), slot 1 -> g=2 (c), slot 2 -> g=3 (o)
__global__ void k_prep(const float* __restrict__ Wx, const float* __restrict__ bx,
                       const float* __restrict__ bh, const float* __restrict__ wc,
                       const float* __restrict__ bg, const float* __restrict__ Wlin,
                       const float* __restrict__ blin) {
    int t = threadIdx.x;
    for (int idx = t; idx < KF * NG; idx += blockDim.x) {
        int k = idx / NG, o = idx % NG;
        int s = o / HIDF, h = o % HIDF;
        int g = (s == 0) ? 0 : ((s == 1) ? 2 : 3);
        int kk = (k < CINF) ? 0 : 1;
        int kr = k & (CINF - 1);
        // Wx: [4][K=2][CIN][HID]
        g_Wc[idx] = Wx[((g * 2 + kk) * CINF + kr) * HIDF + h];
    }
    for (int idx = t; idx < NG; idx += blockDim.x) {
        int s = idx / HIDF, h = idx % HIDF;
        int g = (s == 0) ? 0 : ((s == 1) ? 2 : 3);
        g_bias[idx] = bx[g * HIDF + h] + bh[g * HIDF + h] + bg[g * HIDF + h];
    }
    if (t < HIDF) {
        g_wlin[t] = Wlin[t];         // [HID,1]
        g_wc2[t]  = wc[2 * HIDF + t];
    }
    if (t == 0) g_blin = blin[0];
}

// ---------------- zero accumulators (float4 stores) ----------------
__global__ void k_zero() {
    int i = blockIdx.x * blockDim.x + threadIdx.x;
    float4 z = make_float4(0.f, 0.f, 0.f, 0.f);
    if (i < NN / 4) ((float4*)g_deg)[i] = z;
    if (i < NN * 4) g_tx1[i] = z;
}

// ---------------- degree: 4 edges per thread, batched loads (MLP=4) ----------------
__global__ void __launch_bounds__(256) k_deg(const void* __restrict__ ei,
                                             const float* __restrict__ w) {
    int base = blockIdx.x * 1024 + threadIdx.x;
    int is64 = g_is64;
    int r[4]; float wv[4]; bool ok[4];
    #pragma unroll
    for (int j = 0; j < 4; j++) {
        int e = base + j * 256;
        ok[j] = (e < EE);
        int es = ok[j] ? e : 0;
        r[j]  = is64 ? (int)__ldg(&((const long long*)ei)[es]) : __ldg(&((const int*)ei)[es]);
        wv[j] = __ldg(&w[es]);
    }
    #pragma unroll
    for (int j = 0; j < 4; j++)
        if (ok[j]) atomicAdd(&g_deg[r[j]], wv[j]);
}

__global__ void k_dinv() {
    int i = blockIdx.x * blockDim.x + threadIdx.x;
    if (i < NN) {
        float d = g_deg[i];
        g_deg[i] = (d > 0.f) ? rsqrtf(d) : 0.f;
    }
}

// ---------------- scatter: tx1[row] += (w * dinv[col]) * x[col] ----------------
// dinv[row] factor deferred to the gate kernel. 2 edges/thread, batched loads.
__global__ void __launch_bounds__(256) k_scatter(const void* __restrict__ ei,
                                                 const float* __restrict__ w,
                                                 const float* __restrict__ x) {
    int base = blockIdx.x * 512 + threadIdx.x;
    int is64 = g_is64;
    const float4* x4 = (const float4*)x;

    int r[2], c[2]; float wv[2]; bool ok[2];
    #pragma unroll
    for (int j = 0; j < 2; j++) {
        int e = base + j * 256;
        ok[j] = (e < EE);
        int es = ok[j] ? e : 0;
        if (is64) {
            r[j] = (int)__ldg(&((const long long*)ei)[es]);
            c[j] = (int)__ldg(&((const long long*)ei)[EE + es]);
        } else {
            r[j] = __ldg(&((const int*)ei)[es]);
            c[j] = __ldg(&((const int*)ei)[EE + es]);
        }
        wv[j] = __ldg(&w[es]);
    }
    float nm[2];
    #pragma unroll
    for (int j = 0; j < 2; j++)
        nm[j] = wv[j] * g_deg[c[j]];   // g_deg holds dinv now

    float4 v[2][4];
    #pragma unroll
    for (int j = 0; j < 2; j++) {
        #pragma unroll
        for (int q = 0; q < 4; q++)
            v[j][q] = __ldg(&x4[c[j] * 4 + q]);
    }
    #pragma unroll
    for (int j = 0; j < 2; j++) {
        if (!ok[j] || nm[j] == 0.f) continue;
        float4* dst = &g_tx1[r[j] * 4];
        float s = nm[j];
        #pragma unroll
        for (int q = 0; q < 4; q++) {
            asm volatile("red.global.add.v4.f32 [%0], {%1, %2, %3, %4};"
                         :: "l"(dst + q),
                            "f"(v[j][q].x * s), "f"(v[j][q].y * s),
                            "f"(v[j][q].z * s), "f"(v[j][q].w * s)
                         : "memory");
        }
    }
}

// ---------------- dense gates + LSTM nonlinearity + output projection ----------------
// 192 threads, each owns one gate column (weights in regs). 8-node tile.
// NN % 8 == 0 so no bounds checks inside the tile.
__global__ void __launch_bounds__(192) k_gate(const float* __restrict__ x,
                                              float* __restrict__ out) {
    __shared__ float fsm[KF][8];        // [k][node]
    __shared__ float gsm[8 * NG];       // [node][gatecol]
    __shared__ float hsm[8 * HIDF];     // [node][ch] = H*wlin
    __shared__ float wl[HIDF], w2[HIDF];

    int t = threadIdx.x;
    float w[KF];
    #pragma unroll
    for (int k = 0; k < KF; k++) w[k] = g_Wc[k * NG + t];
    float bias = g_bias[t];
    if (t < HIDF) { wl[t] = g_wlin[t]; w2[t] = g_wc2[t]; }
    float blin = g_blin;
    int wid = t >> 5, lane = t & 31;

    for (int tile = blockIdx.x; tile < NN / 8; tile += gridDim.x) {
        int nbase = tile * 8;
        // ---- load features: 8 nodes x 8 float4 by threads 0..63 ----
        if (t < 64) {
            int j = t >> 3, q = t & 7;
            int node = nbase + j;
            float4 v;
            if (q < 4) {
                v = __ldg(&((const float4*)x)[node * 4 + q]);
            } else {
                v = g_tx1[node * 4 + (q - 4)];
                float s = -g_deg[node];   // fold -dinv[row] here
                v.x *= s; v.y *= s; v.z *= s; v.w *= s;
            }
            int k0 = (q < 4) ? q * 4 : 16 + (q - 4) * 4;
            fsm[k0 + 0][j] = v.x;
            fsm[k0 + 1][j] = v.y;
            fsm[k0 + 2][j] = v.z;
            fsm[k0 + 3][j] = v.w;
        }
        __syncthreads();

        // ---- GEMM: 8 nodes x 32 k, 256 FFMA per thread ----
        float acc[8];
        #pragma unroll
        for (int j = 0; j < 8; j++) acc[j] = bias;
        #pragma unroll
        for (int k = 0; k < KF; k++) {
            float wk = w[k];
            #pragma unroll
            for (int j = 0; j < 8; j++)
                acc[j] = fmaf(fsm[k][j], wk, acc[j]);
        }
        #pragma unroll
        for (int j = 0; j < 8; j++) gsm[j * NG + t] = acc[j];
        __syncthreads();

        // ---- nonlinearity: 512 (node,ch) items over 192 threads ----
        #pragma unroll
        for (int it = 0; it < 3; it++) {
            int id = t + it * 192;
            if (id < 512) {
                int j = id >> 6, ch = id & 63;
                float gi = gsm[j * NG + ch];
                float gc = gsm[j * NG + 64 + ch];
                float go = gsm[j * NG + 128 + ch];
                float I = 1.f / (1.f + __expf(-gi));
                float C = I * tanhf(gc);
                float O = 1.f / (1.f + __expf(-(go + w2[ch] * C)));
                hsm[j * HIDF + ch] = O * tanhf(C) * wl[ch];
            }
        }
        __syncthreads();

        // ---- per-node reduction over 64 ch: warps take nodes round-robin ----
        for (int n = wid; n < 8; n += 6) {
            float p = hsm[n * HIDF + lane] + hsm[n * HIDF + 32 + lane];
            #pragma unroll
            for (int off = 16; off > 0; off >>= 1)
                p += __shfl_xor_sync(0xffffffffu, p, off);
            if (lane == 0) out[nbase + n] = p + blin;
        }
        __syncthreads();
    }
}

// ---------------- launch ----------------
extern "C" void kernel_launch(void* const* d_in, const int* in_sizes, int n_in,
                              void* d_out, int out_size) {
    const float* x    = (const float*)d_in[0];
    const void*  ei   = d_in[1];
    const float* w    = (const float*)d_in[2];
    const float* Wx   = (const float*)d_in[3];
    const float* bx   = (const float*)d_in[4];
    // d_in[5] = Wh: provably unused (H0 = 0)
    const float* bh   = (const float*)d_in[6];
    const float* wc   = (const float*)d_in[7];
    const float* bg   = (const float*)d_in[8];
    const float* Wlin = (const float*)d_in[9];
    const float* blin = (const float*)d_in[10];
    float* out = (float*)d_out;

    k_detect<<<1, 32>>>((const int*)ei);
    k_prep<<<1, 256>>>(Wx, bx, bh, wc, bg, Wlin, blin);
    k_zero<<<(NN * 4 + 255) / 256, 256>>>();
    k_deg<<<(EE + 1023) / 1024, 256>>>(ei, w);
    k_dinv<<<(NN + 255) / 256, 256>>>();
    k_scatter<<<(EE + 511) / 512, 256>>>(ei, w, x);
    k_gate<<<1184, 192>>>(x, out);
}